// round 5
// baseline (speedup 1.0000x reference)
#include <cuda_runtime.h>
#include <float.h>

// ROI max pooling, 2-pass.
// feat: [B=8, H=50, W=50, C=256] fp32 NHWC; rois: [N,5] (img,x1,y1,x2,y2) incl.
// Dataset ROIs are 28x28 with 7x7 pooling -> each bin = aligned 4x4 window:
//   out[roi,br,bc] = max feat[img, y1+4br..+3, x1+4bc..+3].
// Pass A: Hm[b,y,x] = max_{x..x+3} feat[b,y,x']   (x: 0..46)
// Pass B: one 448-thread CTA per (roi, bin-row); thread = (bin, 4 channels),
//         4 independent float4 loads from Hm + 3 maxes + 1 store.
// General fallback (non-28x28 ROI): direct loop over feat.

#define FH 50
#define FW 50
#define CCH 256
#define PH 7
#define PW 7
#define HX 47               // FW - 3
#define NCHUNK 12           // ceil(47/4), hmax chunks of 4 outputs

__device__ float g_hm[8 * FH * HX * CCH];   // 19.3 MB

__device__ __forceinline__ float4 vmax2(float4 a, float4 b) {
    float4 r;
    r.x = fmaxf(a.x, b.x);
    r.y = fmaxf(a.y, b.y);
    r.z = fmaxf(a.z, b.z);
    r.w = fmaxf(a.w, b.w);
    return r;
}

// Pass A: horizontal window-4 max. One CTA = (b, y, chunk of 4 outputs).
__global__ __launch_bounds__(64)
void hmax_kernel(const float* __restrict__ feat)
{
    const int id    = blockIdx.x;           // (b*FH + y)*NCHUNK + chunk
    const int chunk = id % NCHUNK;
    const int by    = id / NCHUNK;          // b*FH + y
    const int x0    = chunk * 4;
    const int coff  = threadIdx.x * 4;

    const float* rowp = feat + (size_t)by * (FW * CCH) + coff;
    float*       outp = g_hm + (size_t)by * (HX * CCH) + coff;

    float4 v[7];
    #pragma unroll
    for (int j = 0; j < 7; ++j) {
        const int x = x0 + j;
        v[j] = (x < FW) ? *reinterpret_cast<const float4*>(rowp + (size_t)x * CCH)
                        : make_float4(-FLT_MAX, -FLT_MAX, -FLT_MAX, -FLT_MAX);
    }

    float4 m01 = vmax2(v[0], v[1]);
    float4 m12 = vmax2(v[1], v[2]);
    float4 m23 = vmax2(v[2], v[3]);
    float4 m34 = vmax2(v[3], v[4]);
    float4 m45 = vmax2(v[4], v[5]);
    float4 m56 = vmax2(v[5], v[6]);

    float4 o0 = vmax2(m01, m23);
    float4 o1 = vmax2(m12, m34);
    float4 o2 = vmax2(m23, m45);
    float4 o3 = vmax2(m34, m56);

    if (x0 + 0 < HX) *reinterpret_cast<float4*>(outp + (size_t)(x0 + 0) * CCH) = o0;
    if (x0 + 1 < HX) *reinterpret_cast<float4*>(outp + (size_t)(x0 + 1) * CCH) = o1;
    if (x0 + 2 < HX) *reinterpret_cast<float4*>(outp + (size_t)(x0 + 2) * CCH) = o2;
    if (x0 + 3 < HX) *reinterpret_cast<float4*>(outp + (size_t)(x0 + 3) * CCH) = o3;
}

// Pass B: one CTA per (roi, bin-row), 448 threads = 7 bins x 64 channel-slots.
__global__ __launch_bounds__(448)
void gather_kernel(const float* __restrict__ feat,
                   const int*   __restrict__ rois,
                   float*       __restrict__ out)
{
    const int roi = blockIdx.x / PH;
    const int br  = blockIdx.x - roi * PH;

    const int t    = threadIdx.x;
    const int bc   = t >> 6;                 // 0..6
    const int coff = (t & 63) * 4;           // channel offset

    const int* r = rois + roi * 5;
    const int img = r[0];
    const int x1  = r[1];
    const int y1  = r[2];
    const int x2  = r[3];
    const int y2  = r[4];
    const int roi_h = y2 - y1 + 1;
    const int roi_w = x2 - x1 + 1;

    float4 m;

    if (roi_h == 28 && roi_w == 28) {
        const int yy = y1 + 4 * br;
        const int xx = x1 + 4 * bc;
        const float* p = g_hm + (((size_t)img * FH + yy) * HX + xx) * CCH + coff;
        const size_t rstride = (size_t)HX * CCH;
        const float4 a = *reinterpret_cast<const float4*>(p);
        const float4 b = *reinterpret_cast<const float4*>(p + rstride);
        const float4 c = *reinterpret_cast<const float4*>(p + 2 * rstride);
        const float4 d = *reinterpret_cast<const float4*>(p + 3 * rstride);
        m = vmax2(vmax2(a, b), vmax2(c, d));
    } else {
        // General fallback: direct max over this bin's pixel range in feat.
        const int rs = (br * roi_h + PH - 1) / PH;
        const int re = (br == PH - 1) ? roi_h : ((br + 1) * roi_h + PH - 1) / PH;
        const int cs = (bc * roi_w + PW - 1) / PW;
        const int ce = (bc == PW - 1) ? roi_w : ((bc + 1) * roi_w + PW - 1) / PW;
        const float* base = feat
            + (((size_t)img * FH + (size_t)y1) * FW + (size_t)x1) * CCH + coff;
        m = make_float4(-FLT_MAX, -FLT_MAX, -FLT_MAX, -FLT_MAX);
        for (int y = rs; y < re; ++y) {
            const float* rowp = base + (size_t)y * (FW * CCH);
            for (int x = cs; x < ce; ++x) {
                const float4 v = *reinterpret_cast<const float4*>(rowp + (size_t)x * CCH);
                m.x = fmaxf(m.x, v.x); m.y = fmaxf(m.y, v.y);
                m.z = fmaxf(m.z, v.z); m.w = fmaxf(m.w, v.w);
            }
        }
    }

    float* o = out + ((size_t)((roi * PH + br) * PW + bc)) * CCH + coff;
    *reinterpret_cast<float4*>(o) = m;
}

extern "C" void kernel_launch(void* const* d_in, const int* in_sizes, int n_in,
                              void* d_out, int out_size)
{
    const float* feat = (const float*)d_in[0];
    const int*   rois = (const int*)d_in[1];
    const int n_rois = in_sizes[1] / 5;
    float* out = (float*)d_out;

    hmax_kernel<<<8 * FH * NCHUNK, 64>>>(feat);
    gather_kernel<<<n_rois * PH, 448>>>(feat, rois, out);
}